// round 1
// baseline (speedup 1.0000x reference)
#include <cuda_runtime.h>
#include <math.h>

#define DM 512
#define NROWS 4096      // B*S = B*M = 2*2048
#define HEADS 8
#define DK 64
#define DFF 2048
#define LN_EPS 1e-6f

// ---------------- scratch (static device allocations, allowed) ----------------
__device__ float g_ln [NROWS * DM];
__device__ float g_q  [NROWS * DM];
__device__ float g_k  [NROWS * DM];
__device__ float g_v  [NROWS * DM];
__device__ float g_att[NROWS * DM];
__device__ float g_res[NROWS * DM];
__device__ float g_ffn[NROWS * DFF];

// ---------------- LayerNorm: one block per row, D=512 ----------------
__global__ __launch_bounds__(256) void ln_kernel(
    const float* __restrict__ x, const float* __restrict__ a,
    const float* __restrict__ b, float* __restrict__ out) {
  int row = blockIdx.x;
  int t = threadIdx.x;
  const float* xr = x + (size_t)row * DM;
  float v0 = xr[t], v1 = xr[t + 256];
  float s = v0 + v1, ss = v0 * v0 + v1 * v1;
  #pragma unroll
  for (int o = 16; o; o >>= 1) {
    s  += __shfl_xor_sync(0xffffffffu, s, o);
    ss += __shfl_xor_sync(0xffffffffu, ss, o);
  }
  __shared__ float sh[16];
  int w = t >> 5;
  if ((t & 31) == 0) { sh[w] = s; sh[w + 8] = ss; }
  __syncthreads();
  float ts = 0.f, tss = 0.f;
  #pragma unroll
  for (int i = 0; i < 8; i++) { ts += sh[i]; tss += sh[i + 8]; }
  float mu  = ts * (1.0f / DM);
  float var = (tss - (float)DM * mu * mu) * (1.0f / (DM - 1));  // ddof=1
  float sd  = sqrtf(fmaxf(var, 0.0f));
  float inv = 1.0f / (sd + LN_EPS);
  float* orow = out + (size_t)row * DM;
  orow[t]       = a[t]       * (v0 - mu) * inv + b[t];
  orow[t + 256] = a[t + 256] * (v1 - mu) * inv + b[t + 256];
}

// ---------------- fp32 GEMM: C[M,N] = A[M,K] @ B[K,N] (+bias)(+resid)(relu) ---
// 128x128 tile, BK=8, 256 threads, 8x8 per thread. All dims multiples of 128/8.
__global__ __launch_bounds__(256) void gemm_kernel(
    const float* __restrict__ A, const float* __restrict__ B,
    const float* __restrict__ bias, const float* __restrict__ resid,
    float* __restrict__ C, int M, int N, int K, int do_relu) {
  __shared__ __align__(16) float Ast[8][132];   // A transposed, +4 pad
  __shared__ __align__(16) float Bs [8][128];
  int tid = threadIdx.x;
  int tx = tid & 15, ty = tid >> 4;
  int row0 = blockIdx.y * 128, col0 = blockIdx.x * 128;

  int a_r = tid >> 1, a_k = (tid & 1) * 4;      // 128 rows x 8 k, float4 per thread
  int b_k = tid >> 5, b_c = (tid & 31) * 4;     // 8 k x 128 cols, float4 per thread

  float acc[8][8];
  #pragma unroll
  for (int i = 0; i < 8; i++)
    #pragma unroll
    for (int j = 0; j < 8; j++) acc[i][j] = 0.f;

  const float* Ap = A + (size_t)row0 * K;
  const float* Bp = B + col0;

  for (int k0 = 0; k0 < K; k0 += 8) {
    float4 av = *(const float4*)(Ap + (size_t)a_r * K + (k0 + a_k));
    float4 bv = *(const float4*)(Bp + (size_t)(k0 + b_k) * N + b_c);
    __syncthreads();
    Ast[a_k + 0][a_r] = av.x;
    Ast[a_k + 1][a_r] = av.y;
    Ast[a_k + 2][a_r] = av.z;
    Ast[a_k + 3][a_r] = av.w;
    *(float4*)&Bs[b_k][b_c] = bv;
    __syncthreads();
    #pragma unroll
    for (int kk = 0; kk < 8; kk++) {
      float4 a0 = *(const float4*)&Ast[kk][ty * 8];
      float4 a1 = *(const float4*)&Ast[kk][ty * 8 + 4];
      float4 b0 = *(const float4*)&Bs [kk][tx * 8];
      float4 b1 = *(const float4*)&Bs [kk][tx * 8 + 4];
      float ar[8] = {a0.x, a0.y, a0.z, a0.w, a1.x, a1.y, a1.z, a1.w};
      float br[8] = {b0.x, b0.y, b0.z, b0.w, b1.x, b1.y, b1.z, b1.w};
      #pragma unroll
      for (int i = 0; i < 8; i++)
        #pragma unroll
        for (int j = 0; j < 8; j++)
          acc[i][j] = fmaf(ar[i], br[j], acc[i][j]);
    }
  }

  #pragma unroll
  for (int i = 0; i < 8; i++) {
    int r = row0 + ty * 8 + i;
    #pragma unroll
    for (int j4 = 0; j4 < 8; j4 += 4) {
      int c = col0 + tx * 8 + j4;
      float4 v = make_float4(acc[i][j4], acc[i][j4 + 1], acc[i][j4 + 2], acc[i][j4 + 3]);
      if (bias) {
        v.x += bias[c]; v.y += bias[c + 1]; v.z += bias[c + 2]; v.w += bias[c + 3];
      }
      if (resid) {
        float4 rv = *(const float4*)(resid + (size_t)r * N + c);
        v.x += rv.x; v.y += rv.y; v.z += rv.z; v.w += rv.w;
      }
      if (do_relu) {
        v.x = fmaxf(v.x, 0.f); v.y = fmaxf(v.y, 0.f);
        v.z = fmaxf(v.z, 0.f); v.w = fmaxf(v.w, 0.f);
      }
      *(float4*)(C + (size_t)r * N + c) = v;
    }
  }
}

// ---------------- Flash attention: 64 q-rows x 64 keys tiles, online softmax --
// Layout: Q/K/V/O are [B*S, 512] with column = h*64 + d.
#define ATT_PAD 68
#define ATT_SMEM (4 * 64 * ATT_PAD * 4)

__global__ __launch_bounds__(256) void attn_kernel(
    const float* __restrict__ Q, const float* __restrict__ K,
    const float* __restrict__ V, float* __restrict__ O,
    int Sq, int Sk, int causal) {
  extern __shared__ __align__(16) float sm[];
  float (*Qt)[ATT_PAD] = (float(*)[ATT_PAD])(sm);                  // [d][row]
  float (*Kt)[ATT_PAD] = (float(*)[ATT_PAD])(sm + 64 * ATT_PAD);   // [d][key]
  float (*Vs)[ATT_PAD] = (float(*)[ATT_PAD])(sm + 2 * 64 * ATT_PAD); // [key][d]
  float (*Ps)[ATT_PAD] = (float(*)[ATT_PAD])(sm + 3 * 64 * ATT_PAD); // [row][key]

  int tid = threadIdx.x, tx = tid & 15, ty = tid >> 4;
  int qt = blockIdx.x, h = blockIdx.y, b = blockIdx.z;
  int q0 = qt * 64;

  const float* Qb = Q + ((size_t)b * Sq) * DM + h * DK;
  const float* Kb = K + ((size_t)b * Sk) * DM + h * DK;
  const float* Vb = V + ((size_t)b * Sk) * DM + h * DK;

  #pragma unroll
  for (int i = 0; i < 16; i++) {
    int e = i * 256 + tid; int r = e >> 6, d = e & 63;
    Qt[d][r] = Qb[(size_t)(q0 + r) * DM + d];
  }

  float m[4], l[4], o[4][4];
  #pragma unroll
  for (int i = 0; i < 4; i++) {
    m[i] = -1e30f; l[i] = 0.f;
    #pragma unroll
    for (int j = 0; j < 4; j++) o[i][j] = 0.f;
  }

  int ntiles = causal ? (qt + 1) : (Sk >> 6);
  const float scale = 0.125f;  // 1/sqrt(64)

  for (int kt = 0; kt < ntiles; kt++) {
    int k0 = kt * 64;
    __syncthreads();
    #pragma unroll
    for (int i = 0; i < 16; i++) {
      int e = i * 256 + tid; int r = e >> 6, d = e & 63;
      Kt[d][r] = Kb[(size_t)(k0 + r) * DM + d];
      Vs[r][d] = Vb[(size_t)(k0 + r) * DM + d];
    }
    __syncthreads();

    float s[4][4];
    #pragma unroll
    for (int i = 0; i < 4; i++)
      #pragma unroll
      for (int j = 0; j < 4; j++) s[i][j] = 0.f;

    #pragma unroll
    for (int d = 0; d < 64; d++) {
      float4 qv = *(const float4*)&Qt[d][ty * 4];
      float4 kv = *(const float4*)&Kt[d][tx * 4];
      float qa[4] = {qv.x, qv.y, qv.z, qv.w};
      float ka[4] = {kv.x, kv.y, kv.z, kv.w};
      #pragma unroll
      for (int i = 0; i < 4; i++)
        #pragma unroll
        for (int j = 0; j < 4; j++)
          s[i][j] = fmaf(qa[i], ka[j], s[i][j]);
    }

    bool diag = (causal != 0) && (kt == qt);
    #pragma unroll
    for (int i = 0; i < 4; i++)
      #pragma unroll
      for (int j = 0; j < 4; j++) {
        s[i][j] *= scale;
        if (diag && (k0 + tx * 4 + j) > (q0 + ty * 4 + i)) s[i][j] = -1e30f;
      }

    #pragma unroll
    for (int i = 0; i < 4; i++) {
      float mx = fmaxf(fmaxf(s[i][0], s[i][1]), fmaxf(s[i][2], s[i][3]));
      #pragma unroll
      for (int off = 8; off; off >>= 1)
        mx = fmaxf(mx, __shfl_xor_sync(0xffffffffu, mx, off));
      float mn = fmaxf(m[i], mx);
      float al = __expf(m[i] - mn);
      float sum = 0.f;
      #pragma unroll
      for (int j = 0; j < 4; j++) {
        float p = __expf(s[i][j] - mn);
        s[i][j] = p; sum += p;
      }
      #pragma unroll
      for (int off = 8; off; off >>= 1)
        sum += __shfl_xor_sync(0xffffffffu, sum, off);
      l[i] = l[i] * al + sum;
      m[i] = mn;
      #pragma unroll
      for (int j = 0; j < 4; j++) o[i][j] *= al;
    }

    #pragma unroll
    for (int i = 0; i < 4; i++)
      *(float4*)&Ps[ty * 4 + i][tx * 4] = make_float4(s[i][0], s[i][1], s[i][2], s[i][3]);
    __syncthreads();

    #pragma unroll
    for (int kk = 0; kk < 64; kk++) {
      float4 vv = *(const float4*)&Vs[kk][tx * 4];
      float va[4] = {vv.x, vv.y, vv.z, vv.w};
      float pa[4];
      #pragma unroll
      for (int i = 0; i < 4; i++) pa[i] = Ps[ty * 4 + i][kk];
      #pragma unroll
      for (int i = 0; i < 4; i++)
        #pragma unroll
        for (int j = 0; j < 4; j++)
          o[i][j] = fmaf(pa[i], va[j], o[i][j]);
    }
  }

  #pragma unroll
  for (int i = 0; i < 4; i++) {
    int r = q0 + ty * 4 + i;
    float inv = 1.0f / l[i];
    float4 v = make_float4(o[i][0] * inv, o[i][1] * inv, o[i][2] * inv, o[i][3] * inv);
    *(float4*)(O + ((size_t)b * Sq + r) * DM + h * DK + tx * 4) = v;
  }
}

// ---------------- launch ----------------
extern "C" void kernel_launch(void* const* d_in, const int* in_sizes, int n_in,
                              void* d_out, int out_size) {
  const float* x    = (const float*)d_in[0];
  const float* mem  = (const float*)d_in[1];
  const float* ln1a = (const float*)d_in[2];
  const float* ln1b = (const float*)d_in[3];
  const float* ln2a = (const float*)d_in[4];
  const float* ln2b = (const float*)d_in[5];
  const float* ln3a = (const float*)d_in[6];
  const float* ln3b = (const float*)d_in[7];
  const float* a1wq = (const float*)d_in[8];
  const float* a1wk = (const float*)d_in[9];
  const float* a1wv = (const float*)d_in[10];
  const float* a1wo = (const float*)d_in[11];
  const float* a1bo = (const float*)d_in[12];
  const float* a2wq = (const float*)d_in[13];
  const float* a2wk = (const float*)d_in[14];
  const float* a2wv = (const float*)d_in[15];
  const float* a2wo = (const float*)d_in[16];
  const float* a2bo = (const float*)d_in[17];
  const float* fw1  = (const float*)d_in[18];
  const float* fb1  = (const float*)d_in[19];
  const float* fw2  = (const float*)d_in[20];
  const float* fb2  = (const float*)d_in[21];
  float* out = (float*)d_out;

  float *p_ln, *p_q, *p_k, *p_v, *p_att, *p_res, *p_ffn;
  cudaGetSymbolAddress((void**)&p_ln,  g_ln);
  cudaGetSymbolAddress((void**)&p_q,   g_q);
  cudaGetSymbolAddress((void**)&p_k,   g_k);
  cudaGetSymbolAddress((void**)&p_v,   g_v);
  cudaGetSymbolAddress((void**)&p_att, g_att);
  cudaGetSymbolAddress((void**)&p_res, g_res);
  cudaGetSymbolAddress((void**)&p_ffn, g_ffn);

  cudaFuncSetAttribute(attn_kernel, cudaFuncAttributeMaxDynamicSharedMemorySize, ATT_SMEM);

  dim3 gP(4, 32);    // N=512 GEMMs
  dim3 gF(16, 32);   // N=2048 GEMM
  dim3 gA(32, HEADS, 2);

  // --- self-attention block ---
  ln_kernel<<<NROWS, 256>>>(x, ln1a, ln1b, p_ln);
  gemm_kernel<<<gP, 256>>>(p_ln, a1wq, nullptr, nullptr, p_q, NROWS, DM, DM, 0);
  gemm_kernel<<<gP, 256>>>(p_ln, a1wk, nullptr, nullptr, p_k, NROWS, DM, DM, 0);
  gemm_kernel<<<gP, 256>>>(p_ln, a1wv, nullptr, nullptr, p_v, NROWS, DM, DM, 0);
  attn_kernel<<<gA, 256, ATT_SMEM>>>(p_q, p_k, p_v, p_att, 2048, 2048, 1);
  gemm_kernel<<<gP, 256>>>(p_att, a1wo, a1bo, x, p_res, NROWS, DM, DM, 0);

  // --- cross-attention block ---
  ln_kernel<<<NROWS, 256>>>(p_res, ln2a, ln2b, p_ln);
  gemm_kernel<<<gP, 256>>>(p_ln, a2wq, nullptr, nullptr, p_q, NROWS, DM, DM, 0);
  gemm_kernel<<<gP, 256>>>(mem,  a2wk, nullptr, nullptr, p_k, NROWS, DM, DM, 0);
  gemm_kernel<<<gP, 256>>>(mem,  a2wv, nullptr, nullptr, p_v, NROWS, DM, DM, 0);
  attn_kernel<<<gA, 256, ATT_SMEM>>>(p_q, p_k, p_v, p_att, 2048, 2048, 0);
  gemm_kernel<<<gP, 256>>>(p_att, a2wo, a2bo, p_res, p_res, NROWS, DM, DM, 0);

  // --- FFN block ---
  ln_kernel<<<NROWS, 256>>>(p_res, ln3a, ln3b, p_ln);
  gemm_kernel<<<gF, 256>>>(p_ln, fw1, fb1, nullptr, p_ffn, NROWS, DFF, DM, 1);
  gemm_kernel<<<gP, 256>>>(p_ffn, fw2, fb2, p_res, out, NROWS, DM, DFF, 0);
}

// round 3
// speedup vs baseline: 4.1909x; 4.1909x over previous
#include <cuda_runtime.h>
#include <math.h>
#include <stdint.h>

#define DM 512
#define NROWS 4096      // B*S = B*M = 2*2048
#define HEADS 8
#define DK 64
#define DFF 2048
#define LN_EPS 1e-6f

// ---------------- scratch ----------------
__device__ float g_ln [NROWS * DM];
__device__ float g_q  [NROWS * DM];
__device__ float g_k  [NROWS * DM];
__device__ float g_v  [NROWS * DM];
__device__ float g_att[NROWS * DM];
__device__ float g_res[NROWS * DM];
__device__ float g_ffn[NROWS * DFF];

// ---------------- helpers ----------------
__device__ __forceinline__ uint32_t f2tf(float x) {
  uint32_t u;
  asm("cvt.rna.tf32.f32 %0, %1;" : "=r"(u) : "f"(x));
  return u;
}
__device__ __forceinline__ float f2tff(float x) { return __uint_as_float(f2tf(x)); }

__device__ __forceinline__ void mma8(float* c, const uint32_t* a, uint32_t b0, uint32_t b1) {
  asm volatile(
      "mma.sync.aligned.m16n8k8.row.col.f32.tf32.tf32.f32 "
      "{%0,%1,%2,%3}, {%4,%5,%6,%7}, {%8,%9}, {%0,%1,%2,%3};\n"
      : "+f"(c[0]), "+f"(c[1]), "+f"(c[2]), "+f"(c[3])
      : "r"(a[0]), "r"(a[1]), "r"(a[2]), "r"(a[3]), "r"(b0), "r"(b1));
}

// ---------------- LayerNorm ----------------
__global__ __launch_bounds__(256) void ln_kernel(
    const float* __restrict__ x, const float* __restrict__ a,
    const float* __restrict__ b, float* __restrict__ out) {
  int row = blockIdx.x;
  int t = threadIdx.x;
  const float* xr = x + (size_t)row * DM;
  float v0 = xr[t], v1 = xr[t + 256];
  float s = v0 + v1, ss = v0 * v0 + v1 * v1;
  #pragma unroll
  for (int o = 16; o; o >>= 1) {
    s  += __shfl_xor_sync(0xffffffffu, s, o);
    ss += __shfl_xor_sync(0xffffffffu, ss, o);
  }
  __shared__ float sh[16];
  int w = t >> 5;
  if ((t & 31) == 0) { sh[w] = s; sh[w + 8] = ss; }
  __syncthreads();
  float ts = 0.f, tss = 0.f;
  #pragma unroll
  for (int i = 0; i < 8; i++) { ts += sh[i]; tss += sh[i + 8]; }
  float mu  = ts * (1.0f / DM);
  float var = (tss - (float)DM * mu * mu) * (1.0f / (DM - 1));  // ddof=1
  float sd  = sqrtf(fmaxf(var, 0.0f));
  float inv = 1.0f / (sd + LN_EPS);
  float* orow = out + (size_t)row * DM;
  orow[t]       = a[t]       * (v0 - mu) * inv + b[t];
  orow[t + 256] = a[t + 256] * (v1 - mu) * inv + b[t + 256];
}

// ---------------- tf32 tensor-core GEMM ----------------
// C[M,N] = A[M,K] @ B[K,N] (+bias)(+resid)(relu). 128x128 tile, BK=32,
// 256 threads (8 warps, 2x4), warp tile 64x32, double-buffered smem.
#define GAP 36    // A smem pitch (floats), m-major [128][36]
#define GBP 136   // B smem pitch (floats), k-major [32][136]
#define GSMEM ((2 * 128 * GAP + 2 * 32 * GBP) * 4)

__global__ __launch_bounds__(256) void gemm_tc(
    const float* __restrict__ A, const float* __restrict__ B,
    const float* __restrict__ bias, const float* __restrict__ resid,
    float* __restrict__ C, int M, int N, int K, int relu) {
  extern __shared__ float sm[];
  float* As = sm;                   // [2][128][GAP]
  float* Bs = sm + 2 * 128 * GAP;   // [2][32][GBP]

  int tid = threadIdx.x;
  int row0 = blockIdx.y * 128, col0 = blockIdx.x * 128;
  int am = tid >> 1, ak = (tid & 1) * 16;    // A: 128 rows x 32 k, 4xfloat4/thread
  int bk = tid >> 3, bn = (tid & 7) * 16;    // B: 32 k x 128 n, 4xfloat4/thread
  const float* Ag = A + (size_t)(row0 + am) * K + ak;
  const float* Bg = B + (size_t)bk * N + col0 + bn;

  int lane = tid & 31, wid = tid >> 5;
  int g = lane >> 2, tg = lane & 3;
  int wm = (wid >> 2) * 64, wn = (wid & 3) * 32;

  float acc[4][4][4];
  #pragma unroll
  for (int i = 0; i < 4; i++)
    #pragma unroll
    for (int j = 0; j < 4; j++)
      #pragma unroll
      for (int k = 0; k < 4; k++) acc[i][j][k] = 0.f;

  float4 ra[4], rb[4];
  // prologue: tile 0
  #pragma unroll
  for (int i = 0; i < 4; i++) {
    ra[i] = *(const float4*)(Ag + 4 * i);
    rb[i] = *(const float4*)(Bg + 4 * i);
  }
  #pragma unroll
  for (int i = 0; i < 4; i++) {
    As[am * GAP + ak + 4 * i + 0] = f2tff(ra[i].x);
    As[am * GAP + ak + 4 * i + 1] = f2tff(ra[i].y);
    As[am * GAP + ak + 4 * i + 2] = f2tff(ra[i].z);
    As[am * GAP + ak + 4 * i + 3] = f2tff(ra[i].w);
    Bs[bk * GBP + bn + 4 * i + 0] = f2tff(rb[i].x);
    Bs[bk * GBP + bn + 4 * i + 1] = f2tff(rb[i].y);
    Bs[bk * GBP + bn + 4 * i + 2] = f2tff(rb[i].z);
    Bs[bk * GBP + bn + 4 * i + 3] = f2tff(rb[i].w);
  }
  __syncthreads();

  int nk = K >> 5;
  for (int kt = 0; kt < nk; kt++) {
    if (kt + 1 < nk) {
      size_t ko = (size_t)(kt + 1) * 32;
      #pragma unroll
      for (int i = 0; i < 4; i++) {
        ra[i] = *(const float4*)(Ag + ko + 4 * i);
        rb[i] = *(const float4*)(Bg + ko * N + 4 * i);
      }
    }
    const float* Ab = As + (kt & 1) * 128 * GAP;
    const float* Bb = Bs + (kt & 1) * 32 * GBP;
    #pragma unroll
    for (int ks = 0; ks < 4; ks++) {
      int k0 = ks * 8;
      uint32_t af[4][4], bf[4][2];
      #pragma unroll
      for (int mt = 0; mt < 4; mt++) {
        int base = (wm + mt * 16 + g) * GAP + k0 + tg;
        af[mt][0] = __float_as_uint(Ab[base]);
        af[mt][1] = __float_as_uint(Ab[base + 8 * GAP]);
        af[mt][2] = __float_as_uint(Ab[base + 4]);
        af[mt][3] = __float_as_uint(Ab[base + 8 * GAP + 4]);
      }
      #pragma unroll
      for (int nt = 0; nt < 4; nt++) {
        int base = (k0 + tg) * GBP + wn + nt * 8 + g;
        bf[nt][0] = __float_as_uint(Bb[base]);
        bf[nt][1] = __float_as_uint(Bb[base + 4 * GBP]);
      }
      #pragma unroll
      for (int mt = 0; mt < 4; mt++)
        #pragma unroll
        for (int nt = 0; nt < 4; nt++)
          mma8(acc[mt][nt], af[mt], bf[nt][0], bf[nt][1]);
    }
    if (kt + 1 < nk) {
      float* Ab2 = As + ((kt + 1) & 1) * 128 * GAP;
      float* Bb2 = Bs + ((kt + 1) & 1) * 32 * GBP;
      #pragma unroll
      for (int i = 0; i < 4; i++) {
        Ab2[am * GAP + ak + 4 * i + 0] = f2tff(ra[i].x);
        Ab2[am * GAP + ak + 4 * i + 1] = f2tff(ra[i].y);
        Ab2[am * GAP + ak + 4 * i + 2] = f2tff(ra[i].z);
        Ab2[am * GAP + ak + 4 * i + 3] = f2tff(ra[i].w);
        Bb2[bk * GBP + bn + 4 * i + 0] = f2tff(rb[i].x);
        Bb2[bk * GBP + bn + 4 * i + 1] = f2tff(rb[i].y);
        Bb2[bk * GBP + bn + 4 * i + 2] = f2tff(rb[i].z);
        Bb2[bk * GBP + bn + 4 * i + 3] = f2tff(rb[i].w);
      }
    }
    __syncthreads();
  }

  // epilogue
  #pragma unroll
  for (int mt = 0; mt < 4; mt++) {
    int r = row0 + wm + mt * 16 + g;
    #pragma unroll
    for (int nt = 0; nt < 4; nt++) {
      int c = col0 + wn + nt * 8 + 2 * tg;
      float2 v0 = make_float2(acc[mt][nt][0], acc[mt][nt][1]);
      float2 v1 = make_float2(acc[mt][nt][2], acc[mt][nt][3]);
      if (bias) {
        float b0 = bias[c], b1 = bias[c + 1];
        v0.x += b0; v0.y += b1; v1.x += b0; v1.y += b1;
      }
      if (resid) {
        float2 r0v = *(const float2*)(resid + (size_t)r * N + c);
        float2 r1v = *(const float2*)(resid + (size_t)(r + 8) * N + c);
        v0.x += r0v.x; v0.y += r0v.y; v1.x += r1v.x; v1.y += r1v.y;
      }
      if (relu) {
        v0.x = fmaxf(v0.x, 0.f); v0.y = fmaxf(v0.y, 0.f);
        v1.x = fmaxf(v1.x, 0.f); v1.y = fmaxf(v1.y, 0.f);
      }
      *(float2*)(C + (size_t)r * N + c) = v0;
      *(float2*)(C + (size_t)(r + 8) * N + c) = v1;
    }
  }
}

// ---------------- tf32 flash attention ----------------
// 64 q-rows x 64 keys per tile, 128 threads (4 warps x 16 rows), online softmax.
#define QP 68
#define KP 68
#define VP 72
#define PP 68
#define ASMEM ((64 * QP + 64 * KP + 64 * VP + 64 * PP) * 4)

__global__ __launch_bounds__(128) void attn_tc(
    const float* __restrict__ Q, const float* __restrict__ K,
    const float* __restrict__ V, float* __restrict__ O,
    int Sq, int Sk, int causal) {
  extern __shared__ float sm[];
  float* Qs = sm;                // [64][QP]
  float* Ks = Qs + 64 * QP;      // [64][KP] (row=key, col=d)
  float* Vs = Ks + 64 * KP;      // [64][VP] (row=key, col=d)
  float* Ps = Vs + 64 * VP;      // [64][PP]

  int tid = threadIdx.x, lane = tid & 31, w = tid >> 5;
  int g = lane >> 2, tg = lane & 3;
  int qt = blockIdx.x, h = blockIdx.y, b = blockIdx.z;
  int q0 = qt * 64;

  const float* Qb = Q + ((size_t)b * Sq + q0) * DM + h * DK;
  const float* Kb = K + ((size_t)b * Sk) * DM + h * DK;
  const float* Vb = V + ((size_t)b * Sk) * DM + h * DK;

  // load Q once
  #pragma unroll
  for (int i = 0; i < 8; i++) {
    int idx = i * 128 + tid;
    int r = idx >> 4, d = (idx & 15) * 4;
    float4 qv = *(const float4*)(Qb + (size_t)r * DM + d);
    Qs[r * QP + d + 0] = f2tff(qv.x);
    Qs[r * QP + d + 1] = f2tff(qv.y);
    Qs[r * QP + d + 2] = f2tff(qv.z);
    Qs[r * QP + d + 3] = f2tff(qv.w);
  }

  float m0 = -1e30f, m1 = -1e30f, l0 = 0.f, l1 = 0.f;
  float oacc[8][4];
  #pragma unroll
  for (int nt = 0; nt < 8; nt++)
    #pragma unroll
    for (int j = 0; j < 4; j++) oacc[nt][j] = 0.f;

  int ntiles = causal ? (qt + 1) : (Sk >> 6);
  const float scale = 0.125f;  // 1/sqrt(64)
  int r0 = q0 + w * 16 + g, r1 = r0 + 8;

  for (int kt = 0; kt < ntiles; kt++) {
    __syncthreads();
    const float* Kg = Kb + (size_t)kt * 64 * DM;
    const float* Vg = Vb + (size_t)kt * 64 * DM;
    #pragma unroll
    for (int i = 0; i < 8; i++) {
      int idx = i * 128 + tid;
      int r = idx >> 4, d = (idx & 15) * 4;
      float4 kv = *(const float4*)(Kg + (size_t)r * DM + d);
      float4 vv = *(const float4*)(Vg + (size_t)r * DM + d);
      Ks[r * KP + d + 0] = f2tff(kv.x);
      Ks[r * KP + d + 1] = f2tff(kv.y);
      Ks[r * KP + d + 2] = f2tff(kv.z);
      Ks[r * KP + d + 3] = f2tff(kv.w);
      Vs[r * VP + d + 0] = f2tff(vv.x);
      Vs[r * VP + d + 1] = f2tff(vv.y);
      Vs[r * VP + d + 2] = f2tff(vv.z);
      Vs[r * VP + d + 3] = f2tff(vv.w);
    }
    __syncthreads();

    // S = Q @ K^T  (warp: 16 rows x 64 cols)
    float sacc[8][4];
    #pragma unroll
    for (int nt = 0; nt < 8; nt++)
      #pragma unroll
      for (int j = 0; j < 4; j++) sacc[nt][j] = 0.f;

    #pragma unroll
    for (int ks = 0; ks < 8; ks++) {
      int k0 = ks * 8;
      int qbase = (w * 16 + g) * QP + k0 + tg;
      uint32_t a[4];
      a[0] = __float_as_uint(Qs[qbase]);
      a[1] = __float_as_uint(Qs[qbase + 8 * QP]);
      a[2] = __float_as_uint(Qs[qbase + 4]);
      a[3] = __float_as_uint(Qs[qbase + 8 * QP + 4]);
      #pragma unroll
      for (int nt = 0; nt < 8; nt++) {
        int kb = (nt * 8 + g) * KP + k0 + tg;
        mma8(sacc[nt], a, __float_as_uint(Ks[kb]), __float_as_uint(Ks[kb + 4]));
      }
    }

    // scale + causal mask
    bool diag = (causal != 0) && (kt == qt);
    #pragma unroll
    for (int nt = 0; nt < 8; nt++) {
      int c = kt * 64 + nt * 8 + 2 * tg;
      float s0 = sacc[nt][0] * scale, s1 = sacc[nt][1] * scale;
      float s2 = sacc[nt][2] * scale, s3 = sacc[nt][3] * scale;
      if (diag) {
        if (c > r0)     s0 = -1e30f;
        if (c + 1 > r0) s1 = -1e30f;
        if (c > r1)     s2 = -1e30f;
        if (c + 1 > r1) s3 = -1e30f;
      }
      sacc[nt][0] = s0; sacc[nt][1] = s1; sacc[nt][2] = s2; sacc[nt][3] = s3;
    }

    // online softmax (rows g and g+8; quad lanes share a row)
    float mx0 = -1e30f, mx1 = -1e30f;
    #pragma unroll
    for (int nt = 0; nt < 8; nt++) {
      mx0 = fmaxf(mx0, fmaxf(sacc[nt][0], sacc[nt][1]));
      mx1 = fmaxf(mx1, fmaxf(sacc[nt][2], sacc[nt][3]));
    }
    mx0 = fmaxf(mx0, __shfl_xor_sync(0xffffffffu, mx0, 1));
    mx0 = fmaxf(mx0, __shfl_xor_sync(0xffffffffu, mx0, 2));
    mx1 = fmaxf(mx1, __shfl_xor_sync(0xffffffffu, mx1, 1));
    mx1 = fmaxf(mx1, __shfl_xor_sync(0xffffffffu, mx1, 2));
    float mn0 = fmaxf(m0, mx0), mn1 = fmaxf(m1, mx1);
    float al0 = __expf(m0 - mn0), al1 = __expf(m1 - mn1);
    m0 = mn0; m1 = mn1;
    float sum0 = 0.f, sum1 = 0.f;
    #pragma unroll
    for (int nt = 0; nt < 8; nt++) {
      float p0 = __expf(sacc[nt][0] - mn0);
      float p1 = __expf(sacc[nt][1] - mn0);
      float p2 = __expf(sacc[nt][2] - mn1);
      float p3 = __expf(sacc[nt][3] - mn1);
      sacc[nt][0] = p0; sacc[nt][1] = p1; sacc[nt][2] = p2; sacc[nt][3] = p3;
      sum0 += p0 + p1; sum1 += p2 + p3;
    }
    sum0 += __shfl_xor_sync(0xffffffffu, sum0, 1);
    sum0 += __shfl_xor_sync(0xffffffffu, sum0, 2);
    sum1 += __shfl_xor_sync(0xffffffffu, sum1, 1);
    sum1 += __shfl_xor_sync(0xffffffffu, sum1, 2);
    l0 = l0 * al0 + sum0;
    l1 = l1 * al1 + sum1;
    #pragma unroll
    for (int nt = 0; nt < 8; nt++) {
      oacc[nt][0] *= al0; oacc[nt][1] *= al0;
      oacc[nt][2] *= al1; oacc[nt][3] *= al1;
    }

    // store P to smem (per-warp region)
    int pb = (w * 16 + g) * PP;
    #pragma unroll
    for (int nt = 0; nt < 8; nt++) {
      int c = nt * 8 + 2 * tg;
      Ps[pb + c]              = f2tff(sacc[nt][0]);
      Ps[pb + c + 1]          = f2tff(sacc[nt][1]);
      Ps[pb + 8 * PP + c]     = f2tff(sacc[nt][2]);
      Ps[pb + 8 * PP + c + 1] = f2tff(sacc[nt][3]);
    }
    __syncwarp();

    // O += P @ V
    #pragma unroll
    for (int ks = 0; ks < 8; ks++) {
      int k0 = ks * 8;
      int pbase = (w * 16 + g) * PP + k0 + tg;
      uint32_t a[4];
      a[0] = __float_as_uint(Ps[pbase]);
      a[1] = __float_as_uint(Ps[pbase + 8 * PP]);
      a[2] = __float_as_uint(Ps[pbase + 4]);
      a[3] = __float_as_uint(Ps[pbase + 8 * PP + 4]);
      #pragma unroll
      for (int nt = 0; nt < 8; nt++) {
        int vb = (k0 + tg) * VP + nt * 8 + g;
        mma8(oacc[nt], a, __float_as_uint(Vs[vb]), __float_as_uint(Vs[vb + 4 * VP]));
      }
    }
  }

  float inv0 = 1.0f / l0, inv1 = 1.0f / l1;
  size_t rowg = (size_t)b * Sq + q0 + w * 16 + g;
  #pragma unroll
  for (int nt = 0; nt < 8; nt++) {
    int c = h * DK + nt * 8 + 2 * tg;
    float2 v0 = make_float2(oacc[nt][0] * inv0, oacc[nt][1] * inv0);
    float2 v1 = make_float2(oacc[nt][2] * inv1, oacc[nt][3] * inv1);
    *(float2*)(O + rowg * DM + c) = v0;
    *(float2*)(O + (rowg + 8) * DM + c) = v1;
  }
}

// ---------------- launch ----------------
extern "C" void kernel_launch(void* const* d_in, const int* in_sizes, int n_in,
                              void* d_out, int out_size) {
  const float* x    = (const float*)d_in[0];
  const float* mem  = (const float*)d_in[1];
  const float* ln1a = (const float*)d_in[2];
  const float* ln1b = (const float*)d_in[3];
  const float* ln2a = (const float*)d_in[4];
  const float* ln2b = (const float*)d_in[5];
  const float* ln3a = (const float*)d_in[6];
  const float* ln3b = (const float*)d_in[7];
  const float* a1wq = (const float*)d_in[8];
  const float* a1wk = (const float*)d_in[9];
  const float* a1wv = (const float*)d_in[10];
  const float* a1wo = (const float*)d_in[11];
  const float* a1bo = (const float*)d_in[12];
  const float* a2wq = (const float*)d_in[13];
  const float* a2wk = (const float*)d_in[14];
  const float* a2wv = (const float*)d_in[15];
  const float* a2wo = (const float*)d_in[16];
  const float* a2bo = (const float*)d_in[17];
  const float* fw1  = (const float*)d_in[18];
  const float* fb1  = (const float*)d_in[19];
  const float* fw2  = (const float*)d_in[20];
  const float* fb2  = (const float*)d_in[21];
  float* out = (float*)d_out;

  float *p_ln, *p_q, *p_k, *p_v, *p_att, *p_res, *p_ffn;
  cudaGetSymbolAddress((void**)&p_ln,  g_ln);
  cudaGetSymbolAddress((void**)&p_q,   g_q);
  cudaGetSymbolAddress((void**)&p_k,   g_k);
  cudaGetSymbolAddress((void**)&p_v,   g_v);
  cudaGetSymbolAddress((void**)&p_att, g_att);
  cudaGetSymbolAddress((void**)&p_res, g_res);
  cudaGetSymbolAddress((void**)&p_ffn, g_ffn);

  cudaFuncSetAttribute(gemm_tc, cudaFuncAttributeMaxDynamicSharedMemorySize, GSMEM);
  cudaFuncSetAttribute(attn_tc, cudaFuncAttributeMaxDynamicSharedMemorySize, ASMEM);

  dim3 gP(4, 32);    // N=512 GEMMs
  dim3 gF(16, 32);   // N=2048 GEMM
  dim3 gA(32, HEADS, 2);

  // --- self-attention block ---
  ln_kernel<<<NROWS, 256>>>(x, ln1a, ln1b, p_ln);
  gemm_tc<<<gP, 256, GSMEM>>>(p_ln, a1wq, nullptr, nullptr, p_q, NROWS, DM, DM, 0);
  gemm_tc<<<gP, 256, GSMEM>>>(p_ln, a1wk, nullptr, nullptr, p_k, NROWS, DM, DM, 0);
  gemm_tc<<<gP, 256, GSMEM>>>(p_ln, a1wv, nullptr, nullptr, p_v, NROWS, DM, DM, 0);
  attn_tc<<<gA, 128, ASMEM>>>(p_q, p_k, p_v, p_att, 2048, 2048, 1);
  gemm_tc<<<gP, 256, GSMEM>>>(p_att, a1wo, a1bo, x, p_res, NROWS, DM, DM, 0);

  // --- cross-attention block ---
  ln_kernel<<<NROWS, 256>>>(p_res, ln2a, ln2b, p_ln);
  gemm_tc<<<gP, 256, GSMEM>>>(p_ln, a2wq, nullptr, nullptr, p_q, NROWS, DM, DM, 0);
  gemm_tc<<<gP, 256, GSMEM>>>(mem,  a2wk, nullptr, nullptr, p_k, NROWS, DM, DM, 0);
  gemm_tc<<<gP, 256, GSMEM>>>(mem,  a2wv, nullptr, nullptr, p_v, NROWS, DM, DM, 0);
  attn_tc<<<gA, 128, ASMEM>>>(p_q, p_k, p_v, p_att, 2048, 2048, 0);
  gemm_tc<<<gP, 256, GSMEM>>>(p_att, a2wo, a2bo, p_res, p_res, NROWS, DM, DM, 0);

  // --- FFN block ---
  ln_kernel<<<NROWS, 256>>>(p_res, ln3a, ln3b, p_ln);
  gemm_tc<<<gF, 256, GSMEM>>>(p_ln, fw1, fb1, nullptr, p_ffn, NROWS, DFF, DM, 1);
  gemm_tc<<<gP, 256, GSMEM>>>(p_ffn, fw2, fb2, p_res, out, NROWS, DM, DFF, 0);
}

// round 4
// speedup vs baseline: 6.3742x; 1.5209x over previous
#include <cuda_runtime.h>
#include <math.h>
#include <stdint.h>

#define DM 512
#define NROWS 4096      // B*S = B*M = 2*2048
#define HEADS 8
#define DK 64
#define DFF 2048
#define LN_EPS 1e-6f

// ---------------- scratch ----------------
__device__ float g_ln [NROWS * DM];
__device__ float g_q  [NROWS * DM];
__device__ float g_k  [NROWS * DM];
__device__ float g_v  [NROWS * DM];
__device__ float g_att[NROWS * DM];
__device__ float g_res[NROWS * DM];
__device__ float g_ffn[NROWS * DFF];

// ---------------- helpers ----------------
__device__ __forceinline__ uint32_t smaddr(const void* p) {
  return (uint32_t)__cvta_generic_to_shared(p);
}
#define CP16(dst, src) asm volatile("cp.async.cg.shared.global [%0], [%1], 16;\n" :: "r"(dst), "l"(src))
#define CPCOMMIT() asm volatile("cp.async.commit_group;\n")
#define CPWAIT(n)  asm volatile("cp.async.wait_group %0;\n" :: "n"(n))

__device__ __forceinline__ void mma8(float* c, const uint32_t* a, uint32_t b0, uint32_t b1) {
  asm volatile(
      "mma.sync.aligned.m16n8k8.row.col.f32.tf32.tf32.f32 "
      "{%0,%1,%2,%3}, {%4,%5,%6,%7}, {%8,%9}, {%0,%1,%2,%3};\n"
      : "+f"(c[0]), "+f"(c[1]), "+f"(c[2]), "+f"(c[3])
      : "r"(a[0]), "r"(a[1]), "r"(a[2]), "r"(a[3]), "r"(b0), "r"(b1));
}

// ---------------- LayerNorm ----------------
__global__ __launch_bounds__(256) void ln_kernel(
    const float* __restrict__ x, const float* __restrict__ a,
    const float* __restrict__ b, float* __restrict__ out) {
  int row = blockIdx.x;
  int t = threadIdx.x;
  const float* xr = x + (size_t)row * DM;
  float v0 = xr[t], v1 = xr[t + 256];
  float s = v0 + v1, ss = v0 * v0 + v1 * v1;
  #pragma unroll
  for (int o = 16; o; o >>= 1) {
    s  += __shfl_xor_sync(0xffffffffu, s, o);
    ss += __shfl_xor_sync(0xffffffffu, ss, o);
  }
  __shared__ float sh[16];
  int w = t >> 5;
  if ((t & 31) == 0) { sh[w] = s; sh[w + 8] = ss; }
  __syncthreads();
  float ts = 0.f, tss = 0.f;
  #pragma unroll
  for (int i = 0; i < 8; i++) { ts += sh[i]; tss += sh[i + 8]; }
  float mu  = ts * (1.0f / DM);
  float var = (tss - (float)DM * mu * mu) * (1.0f / (DM - 1));  // ddof=1
  float sd  = sqrtf(fmaxf(var, 0.0f));
  float inv = 1.0f / (sd + LN_EPS);
  float* orow = out + (size_t)row * DM;
  orow[t]       = a[t]       * (v0 - mu) * inv + b[t];
  orow[t + 256] = a[t + 256] * (v1 - mu) * inv + b[t + 256];
}

// ---------------- tf32 GEMM, cp.async 3-stage, warp tile 64x64 ----------------
// C[4096,N] = A[4096,K] @ B[K,N] (+bias)(+resid)(relu). CTA tile 128x128, BK=32,
// 128 threads (4 warps 2x2, each 64x64). Up to 3 fused weight matrices selected
// by blockIdx.x / ctiles.
#define STG 3
#define AP 36     // A smem pitch -> bank 4g+tg conflict-free
#define BP 136    // B smem pitch -> bank 8tg+g conflict-free
#define STAGE_F (128 * AP + 32 * BP)   // 8960 floats
#define GSMEM (STG * STAGE_F * 4)      // 107520 B

__global__ __launch_bounds__(128, 2) void gemm_tc(
    const float* __restrict__ A,
    const float* __restrict__ B0, const float* __restrict__ B1, const float* __restrict__ B2,
    const float* __restrict__ bias, const float* __restrict__ resid,
    float* __restrict__ C0, float* __restrict__ C1, float* __restrict__ C2,
    int N, int K, int ctiles, int relu) {
  extern __shared__ float sm[];
  int bx = blockIdx.x;
  int wsel = bx / ctiles;
  int col0 = (bx - wsel * ctiles) * 128;
  const float* B = (wsel == 0) ? B0 : (wsel == 1 ? B1 : B2);
  float* C       = (wsel == 0) ? C0 : (wsel == 1 ? C1 : C2);
  int row0 = blockIdx.y * 128;
  int tid = threadIdx.x, lane = tid & 31, wid = tid >> 5;
  int g = lane >> 2, tg = lane & 3;
  int wm = (wid >> 1) * 64, wn = (wid & 1) * 64;

  float acc[4][8][4];
  #pragma unroll
  for (int i = 0; i < 4; i++)
    #pragma unroll
    for (int j = 0; j < 8; j++)
      #pragma unroll
      for (int k = 0; k < 4; k++) acc[i][j][k] = 0.f;

  auto issue = [&](int s, int kt2) {
    float* As = sm + s * STAGE_F;
    float* Bs = As + 128 * AP;
    int k0 = kt2 * 32;
    #pragma unroll
    for (int i = 0; i < 8; i++) {
      int ch = i * 128 + tid;
      int r = ch >> 3, c = (ch & 7) * 4;
      CP16(smaddr(As + r * AP + c), A + (size_t)(row0 + r) * K + k0 + c);
    }
    #pragma unroll
    for (int i = 0; i < 8; i++) {
      int ch = i * 128 + tid;
      int kr = ch >> 5, c = (ch & 31) * 4;
      CP16(smaddr(Bs + kr * BP + c), B + (size_t)(k0 + kr) * N + col0 + c);
    }
  };

  int nk = K >> 5;
  #pragma unroll
  for (int s = 0; s < STG - 1; s++) {
    if (s < nk) issue(s, s);
    CPCOMMIT();
  }

  for (int kt = 0; kt < nk; kt++) {
    CPWAIT(STG - 2);
    __syncthreads();
    int nx = kt + STG - 1;
    if (nx < nk) issue(nx % STG, nx);
    CPCOMMIT();

    const float* As = sm + (kt % STG) * STAGE_F;
    const float* Bs = As + 128 * AP;
    #pragma unroll
    for (int ks = 0; ks < 4; ks++) {
      int k0 = ks * 8;
      uint32_t af[4][4];
      #pragma unroll
      for (int mt = 0; mt < 4; mt++) {
        const float* ap = As + (wm + mt * 16 + g) * AP + k0 + tg;
        af[mt][0] = __float_as_uint(ap[0]);
        af[mt][1] = __float_as_uint(ap[8 * AP]);
        af[mt][2] = __float_as_uint(ap[4]);
        af[mt][3] = __float_as_uint(ap[8 * AP + 4]);
      }
      #pragma unroll
      for (int nt = 0; nt < 8; nt++) {
        const float* bp = Bs + (k0 + tg) * BP + wn + nt * 8 + g;
        uint32_t b0 = __float_as_uint(bp[0]);
        uint32_t b1 = __float_as_uint(bp[4 * BP]);
        #pragma unroll
        for (int mt = 0; mt < 4; mt++)
          mma8(acc[mt][nt], af[mt], b0, b1);
      }
    }
  }

  // epilogue
  #pragma unroll
  for (int mt = 0; mt < 4; mt++) {
    int r = row0 + wm + mt * 16 + g;
    #pragma unroll
    for (int nt = 0; nt < 8; nt++) {
      int c = col0 + wn + nt * 8 + 2 * tg;
      float2 v0 = make_float2(acc[mt][nt][0], acc[mt][nt][1]);
      float2 v1 = make_float2(acc[mt][nt][2], acc[mt][nt][3]);
      if (bias) {
        float b0 = bias[c], b1 = bias[c + 1];
        v0.x += b0; v0.y += b1; v1.x += b0; v1.y += b1;
      }
      if (resid) {
        float2 r0v = *(const float2*)(resid + (size_t)r * N + c);
        float2 r1v = *(const float2*)(resid + (size_t)(r + 8) * N + c);
        v0.x += r0v.x; v0.y += r0v.y; v1.x += r1v.x; v1.y += r1v.y;
      }
      if (relu) {
        v0.x = fmaxf(v0.x, 0.f); v0.y = fmaxf(v0.y, 0.f);
        v1.x = fmaxf(v1.x, 0.f); v1.y = fmaxf(v1.y, 0.f);
      }
      *(float2*)(C + (size_t)r * N + c) = v0;
      *(float2*)(C + (size_t)(r + 8) * N + c) = v1;
    }
  }
}

// ---------------- tf32 flash attention, Q-tile 128, warp 32x64 ----------------
#define QP 68
#define KP 68
#define VP 72
#define PP 68
#define AQ_F (128 * QP)
#define AK_F (64 * KP)
#define AV_F (64 * VP)
#define ASMEM ((AQ_F + AK_F + AV_F + 128 * PP) * 4)

__global__ __launch_bounds__(128, 2) void attn_tc(
    const float* __restrict__ Q, const float* __restrict__ K,
    const float* __restrict__ V, float* __restrict__ O, int causal) {
  extern __shared__ float sm[];
  float* Qs = sm;
  float* Ks = Qs + AQ_F;
  float* Vs = Ks + AK_F;
  float* Ps = Vs + AV_F;

  int tid = threadIdx.x, lane = tid & 31, w = tid >> 5;
  int g = lane >> 2, tg = lane & 3;
  int qt = blockIdx.x, h = blockIdx.y, b = blockIdx.z;
  int q0 = qt * 128;

  const float* Qb = Q + ((size_t)b * 2048 + q0) * DM + h * DK;
  const float* Kb = K + ((size_t)b * 2048) * DM + h * DK;
  const float* Vb = V + ((size_t)b * 2048) * DM + h * DK;

  // load Q once (async)
  #pragma unroll
  for (int i = 0; i < 16; i++) {
    int ch = i * 128 + tid;
    int r = ch >> 4, c = (ch & 15) * 4;
    CP16(smaddr(Qs + r * QP + c), Qb + (size_t)r * DM + c);
  }
  CPCOMMIT();

  float m[2][2], l[2][2], oacc[2][8][4];
  #pragma unroll
  for (int mt = 0; mt < 2; mt++) {
    m[mt][0] = -1e30f; m[mt][1] = -1e30f;
    l[mt][0] = 0.f; l[mt][1] = 0.f;
    #pragma unroll
    for (int nt = 0; nt < 8; nt++)
      #pragma unroll
      for (int j = 0; j < 4; j++) oacc[mt][nt][j] = 0.f;
  }

  int ntiles = causal ? (2 * qt + 2) : 32;
  const float scale = 0.125f;  // 1/sqrt(64)
  int rb = q0 + w * 32;

  for (int kt = 0; kt < ntiles; kt++) {
    int k0 = kt * 64;
    __syncthreads();
    #pragma unroll
    for (int i = 0; i < 8; i++) {
      int ch = i * 128 + tid;
      int r = ch >> 4, c = (ch & 15) * 4;
      CP16(smaddr(Ks + r * KP + c), Kb + (size_t)(k0 + r) * DM + c);
      CP16(smaddr(Vs + r * VP + c), Vb + (size_t)(k0 + r) * DM + c);
    }
    CPCOMMIT();
    CPWAIT(0);
    __syncthreads();

    // S = Q @ K^T  (warp: 32 rows x 64 cols)
    float sacc[2][8][4];
    #pragma unroll
    for (int mt = 0; mt < 2; mt++)
      #pragma unroll
      for (int nt = 0; nt < 8; nt++)
        #pragma unroll
        for (int j = 0; j < 4; j++) sacc[mt][nt][j] = 0.f;

    #pragma unroll
    for (int ks = 0; ks < 8; ks++) {
      int d0 = ks * 8;
      uint32_t af[2][4];
      #pragma unroll
      for (int mt = 0; mt < 2; mt++) {
        const float* ap = Qs + (w * 32 + mt * 16 + g) * QP + d0 + tg;
        af[mt][0] = __float_as_uint(ap[0]);
        af[mt][1] = __float_as_uint(ap[8 * QP]);
        af[mt][2] = __float_as_uint(ap[4]);
        af[mt][3] = __float_as_uint(ap[8 * QP + 4]);
      }
      #pragma unroll
      for (int nt = 0; nt < 8; nt++) {
        const float* kp = Ks + (nt * 8 + g) * KP + d0 + tg;
        uint32_t b0 = __float_as_uint(kp[0]);
        uint32_t b1 = __float_as_uint(kp[4]);
        #pragma unroll
        for (int mt = 0; mt < 2; mt++)
          mma8(sacc[mt][nt], af[mt], b0, b1);
      }
    }

    bool needm = (causal != 0) && (kt >= 2 * qt);
    #pragma unroll
    for (int mt = 0; mt < 2; mt++) {
      int r0 = rb + mt * 16 + g, r1 = r0 + 8;
      #pragma unroll
      for (int nt = 0; nt < 8; nt++) {
        int c = k0 + nt * 8 + 2 * tg;
        float s0 = sacc[mt][nt][0] * scale, s1 = sacc[mt][nt][1] * scale;
        float s2 = sacc[mt][nt][2] * scale, s3 = sacc[mt][nt][3] * scale;
        if (needm) {
          if (c > r0)     s0 = -1e30f;
          if (c + 1 > r0) s1 = -1e30f;
          if (c > r1)     s2 = -1e30f;
          if (c + 1 > r1) s3 = -1e30f;
        }
        sacc[mt][nt][0] = s0; sacc[mt][nt][1] = s1;
        sacc[mt][nt][2] = s2; sacc[mt][nt][3] = s3;
      }

      float mx0 = -1e30f, mx1 = -1e30f;
      #pragma unroll
      for (int nt = 0; nt < 8; nt++) {
        mx0 = fmaxf(mx0, fmaxf(sacc[mt][nt][0], sacc[mt][nt][1]));
        mx1 = fmaxf(mx1, fmaxf(sacc[mt][nt][2], sacc[mt][nt][3]));
      }
      mx0 = fmaxf(mx0, __shfl_xor_sync(0xffffffffu, mx0, 1));
      mx0 = fmaxf(mx0, __shfl_xor_sync(0xffffffffu, mx0, 2));
      mx1 = fmaxf(mx1, __shfl_xor_sync(0xffffffffu, mx1, 1));
      mx1 = fmaxf(mx1, __shfl_xor_sync(0xffffffffu, mx1, 2));
      float mn0 = fmaxf(m[mt][0], mx0), mn1 = fmaxf(m[mt][1], mx1);
      float al0 = __expf(m[mt][0] - mn0), al1 = __expf(m[mt][1] - mn1);
      m[mt][0] = mn0; m[mt][1] = mn1;
      float sum0 = 0.f, sum1 = 0.f;
      #pragma unroll
      for (int nt = 0; nt < 8; nt++) {
        float p0 = __expf(sacc[mt][nt][0] - mn0);
        float p1 = __expf(sacc[mt][nt][1] - mn0);
        float p2 = __expf(sacc[mt][nt][2] - mn1);
        float p3 = __expf(sacc[mt][nt][3] - mn1);
        sacc[mt][nt][0] = p0; sacc[mt][nt][1] = p1;
        sacc[mt][nt][2] = p2; sacc[mt][nt][3] = p3;
        sum0 += p0 + p1; sum1 += p2 + p3;
      }
      sum0 += __shfl_xor_sync(0xffffffffu, sum0, 1);
      sum0 += __shfl_xor_sync(0xffffffffu, sum0, 2);
      sum1 += __shfl_xor_sync(0xffffffffu, sum1, 1);
      sum1 += __shfl_xor_sync(0xffffffffu, sum1, 2);
      l[mt][0] = l[mt][0] * al0 + sum0;
      l[mt][1] = l[mt][1] * al1 + sum1;
      #pragma unroll
      for (int nt = 0; nt < 8; nt++) {
        oacc[mt][nt][0] *= al0; oacc[mt][nt][1] *= al0;
        oacc[mt][nt][2] *= al1; oacc[mt][nt][3] *= al1;
      }

      int pb = (w * 32 + mt * 16 + g) * PP;
      #pragma unroll
      for (int nt = 0; nt < 8; nt++) {
        int c = nt * 8 + 2 * tg;
        Ps[pb + c]              = sacc[mt][nt][0];
        Ps[pb + c + 1]          = sacc[mt][nt][1];
        Ps[pb + 8 * PP + c]     = sacc[mt][nt][2];
        Ps[pb + 8 * PP + c + 1] = sacc[mt][nt][3];
      }
    }
    __syncwarp();

    // O += P @ V
    #pragma unroll
    for (int ks = 0; ks < 8; ks++) {
      int kk = ks * 8;
      uint32_t af[2][4];
      #pragma unroll
      for (int mt = 0; mt < 2; mt++) {
        const float* ap = Ps + (w * 32 + mt * 16 + g) * PP + kk + tg;
        af[mt][0] = __float_as_uint(ap[0]);
        af[mt][1] = __float_as_uint(ap[8 * PP]);
        af[mt][2] = __float_as_uint(ap[4]);
        af[mt][3] = __float_as_uint(ap[8 * PP + 4]);
      }
      #pragma unroll
      for (int nt = 0; nt < 8; nt++) {
        const float* vp = Vs + (kk + tg) * VP + nt * 8 + g;
        uint32_t b0 = __float_as_uint(vp[0]);
        uint32_t b1 = __float_as_uint(vp[4 * VP]);
        #pragma unroll
        for (int mt = 0; mt < 2; mt++)
          mma8(oacc[mt][nt], af[mt], b0, b1);
      }
    }
  }

  #pragma unroll
  for (int mt = 0; mt < 2; mt++) {
    float inv0 = 1.0f / l[mt][0], inv1 = 1.0f / l[mt][1];
    size_t r = (size_t)b * 2048 + q0 + w * 32 + mt * 16 + g;
    #pragma unroll
    for (int nt = 0; nt < 8; nt++) {
      int c = h * DK + nt * 8 + 2 * tg;
      float2 v0 = make_float2(oacc[mt][nt][0] * inv0, oacc[mt][nt][1] * inv0);
      float2 v1 = make_float2(oacc[mt][nt][2] * inv1, oacc[mt][nt][3] * inv1);
      *(float2*)(O + r * DM + c) = v0;
      *(float2*)(O + (r + 8) * DM + c) = v1;
    }
  }
}

// ---------------- launch ----------------
extern "C" void kernel_launch(void* const* d_in, const int* in_sizes, int n_in,
                              void* d_out, int out_size) {
  const float* x    = (const float*)d_in[0];
  const float* mem  = (const float*)d_in[1];
  const float* ln1a = (const float*)d_in[2];
  const float* ln1b = (const float*)d_in[3];
  const float* ln2a = (const float*)d_in[4];
  const float* ln2b = (const float*)d_in[5];
  const float* ln3a = (const float*)d_in[6];
  const float* ln3b = (const float*)d_in[7];
  const float* a1wq = (const float*)d_in[8];
  const float* a1wk = (const float*)d_in[9];
  const float* a1wv = (const float*)d_in[10];
  const float* a1wo = (const float*)d_in[11];
  const float* a1bo = (const float*)d_in[12];
  const float* a2wq = (const float*)d_in[13];
  const float* a2wk = (const float*)d_in[14];
  const float* a2wv = (const float*)d_in[15];
  const float* a2wo = (const float*)d_in[16];
  const float* a2bo = (const float*)d_in[17];
  const float* fw1  = (const float*)d_in[18];
  const float* fb1  = (const float*)d_in[19];
  const float* fw2  = (const float*)d_in[20];
  const float* fb2  = (const float*)d_in[21];
  float* out = (float*)d_out;

  float *p_ln, *p_q, *p_k, *p_v, *p_att, *p_res, *p_ffn;
  cudaGetSymbolAddress((void**)&p_ln,  g_ln);
  cudaGetSymbolAddress((void**)&p_q,   g_q);
  cudaGetSymbolAddress((void**)&p_k,   g_k);
  cudaGetSymbolAddress((void**)&p_v,   g_v);
  cudaGetSymbolAddress((void**)&p_att, g_att);
  cudaGetSymbolAddress((void**)&p_res, g_res);
  cudaGetSymbolAddress((void**)&p_ffn, g_ffn);

  cudaFuncSetAttribute(gemm_tc, cudaFuncAttributeMaxDynamicSharedMemorySize, GSMEM);
  cudaFuncSetAttribute(attn_tc, cudaFuncAttributeMaxDynamicSharedMemorySize, ASMEM);

  dim3 gQKV(12, 32);  // 3 weights x 4 col tiles
  dim3 gKV(8, 32);    // 2 weights x 4 col tiles
  dim3 gP(4, 32);     // N=512 single
  dim3 gF1(16, 32);   // N=2048 single
  dim3 gA(16, HEADS, 2);

  // --- self-attention block ---
  ln_kernel<<<NROWS, 256>>>(x, ln1a, ln1b, p_ln);
  gemm_tc<<<gQKV, 128, GSMEM>>>(p_ln, a1wq, a1wk, a1wv, nullptr, nullptr,
                                p_q, p_k, p_v, DM, DM, 4, 0);
  attn_tc<<<gA, 128, ASMEM>>>(p_q, p_k, p_v, p_att, 1);
  gemm_tc<<<gP, 128, GSMEM>>>(p_att, a1wo, a1wo, a1wo, a1bo, x,
                              p_res, p_res, p_res, DM, DM, 4, 0);

  // --- cross-attention block ---
  ln_kernel<<<NROWS, 256>>>(p_res, ln2a, ln2b, p_ln);
  gemm_tc<<<gP, 128, GSMEM>>>(p_ln, a2wq, a2wq, a2wq, nullptr, nullptr,
                              p_q, p_q, p_q, DM, DM, 4, 0);
  gemm_tc<<<gKV, 128, GSMEM>>>(mem, a2wk, a2wv, a2wv, nullptr, nullptr,
                               p_k, p_v, p_v, DM, DM, 4, 0);
  attn_tc<<<gA, 128, ASMEM>>>(p_q, p_k, p_v, p_att, 0);
  gemm_tc<<<gP, 128, GSMEM>>>(p_att, a2wo, a2wo, a2wo, a2bo, p_res,
                              p_res, p_res, p_res, DM, DM, 4, 0);

  // --- FFN block ---
  ln_kernel<<<NROWS, 256>>>(p_res, ln3a, ln3b, p_ln);
  gemm_tc<<<gF1, 128, GSMEM>>>(p_ln, fw1, fw1, fw1, fb1, nullptr,
                               p_ffn, p_ffn, p_ffn, DFF, DM, 16, 1);
  gemm_tc<<<gP, 128, GSMEM>>>(p_ffn, fw2, fw2, fw2, fb2, p_res,
                              out, out, out, DM, DFF, 4, 0);
}